// round 1
// baseline (speedup 1.0000x reference)
#include <cuda_runtime.h>
#include <cuda_bf16.h>

#define NN 20000
#define DD 256
#define D4 64          // DD/4
#define EE 640000

// ---------------- static device scratch (no allocations allowed) ----------------
// g_cnt layout: [0,2N) cnt_out[rel], [2N,4N) cnt_in[rel], [4N,6N) cursor[rel]
__device__ int   g_cnt[6 * NN];
__device__ int   g_off[2 * (NN + 1)];
__device__ int   g_csr[2 * EE];
// g_rs layout: [0,2N) rs_out[rel], [2N,4N) rs_in[rel]
__device__ float g_rs[4 * NN];
__device__ __align__(16) float g_aggS[NN * DD];
__device__ __align__(16) float g_aggU[NN * DD];
__device__ __align__(16) float g_h[NN * DD];

// ---------------- setup kernels ----------------
__global__ void k_zero_cnt() {
    int i = blockIdx.x * blockDim.x + threadIdx.x;
    if (i < 6 * NN) g_cnt[i] = 0;
}

__global__ void k_hist(const int* __restrict__ src, const int* __restrict__ dst, int rel) {
    int i = blockIdx.x * blockDim.x + threadIdx.x;
    if (i >= EE) return;
    atomicAdd(&g_cnt[rel * NN + src[i]], 1);            // out-degree (src)
    atomicAdd(&g_cnt[2 * NN + rel * NN + dst[i]], 1);   // in-degree  (dst)
}

// exclusive scan of in-degree counts -> CSR row offsets. One block per relation.
__global__ void k_scan() {
    int rel = blockIdx.x;
    const int* cnt = g_cnt + 2 * NN + rel * NN;
    int* off = g_off + rel * (NN + 1);
    __shared__ int sm[1024];
    __shared__ int s_run;
    int tid = threadIdx.x;
    if (tid == 0) { s_run = 0; off[0] = 0; }
    __syncthreads();
    for (int base = 0; base < NN; base += 1024) {
        int i = base + tid;
        int v = (i < NN) ? cnt[i] : 0;
        sm[tid] = v;
        __syncthreads();
        for (int s = 1; s < 1024; s <<= 1) {
            int t = (tid >= s) ? sm[tid - s] : 0;
            __syncthreads();
            sm[tid] += t;
            __syncthreads();
        }
        if (i < NN) off[i + 1] = s_run + sm[tid];
        __syncthreads();
        if (tid == 0) s_run += sm[1023];
        __syncthreads();
    }
}

__global__ void k_fill(const int* __restrict__ src, const int* __restrict__ dst, int rel) {
    int i = blockIdx.x * blockDim.x + threadIdx.x;
    if (i >= EE) return;
    int d = dst[i];
    int pos = atomicAdd(&g_cnt[4 * NN + rel * NN + d], 1);
    g_csr[rel * EE + g_off[rel * (NN + 1) + d] + pos] = src[i];
}

__global__ void k_rs() {
    int i = blockIdx.x * blockDim.x + threadIdx.x;
    if (i >= NN) return;
#pragma unroll
    for (int rel = 0; rel < 2; rel++) {
        float co = (float)g_cnt[rel * NN + i];
        float ci = (float)g_cnt[2 * NN + rel * NN + i];
        g_rs[rel * NN + i]          = rsqrtf(fmaxf(co, 1.0f));
        g_rs[2 * NN + rel * NN + i] = rsqrtf(fmaxf(ci, 1.0f));
    }
}

// ---------------- aggregation: agg[dst] = rs_in[dst] * sum_e rs_out[src] * x[src] ----------------
// 64 threads per node (one float4 chunk per thread), 4 nodes per 256-thread block.
__global__ void k_agg(const float* __restrict__ xext, int rel, int use_h, int out_sel) {
    int node = blockIdx.x * 4 + (threadIdx.x >> 6);
    int t = threadIdx.x & 63;
    if (node >= NN) return;

    const float4* x4 = (const float4*)(use_h ? (const float*)g_h : xext);
    float4* agg4 = (float4*)(out_sel ? g_aggU : g_aggS);
    const int* off = g_off + rel * (NN + 1);
    const int* csr = g_csr + rel * EE;
    const float* rs_out = g_rs + rel * NN;

    int beg = off[node], end = off[node + 1];
    float4 acc = make_float4(0.f, 0.f, 0.f, 0.f);
    for (int e = beg; e < end; e++) {
        int s = __ldg(&csr[e]);
        float sc = __ldg(&rs_out[s]);
        float4 v = __ldg(&x4[(size_t)s * D4 + t]);
        acc.x += v.x * sc; acc.y += v.y * sc; acc.z += v.z * sc; acc.w += v.w * sc;
    }
    float ri = g_rs[2 * NN + rel * NN + node];
    acc.x *= ri; acc.y *= ri; acc.z *= ri; acc.w *= ri;
    agg4[(size_t)node * D4 + t] = acc;
}

// ---------------- fused dual GEMM + bias (+relu): C = aggS@W0 + aggU@W1 + b0 + b1 ----------------
// BM=64, BN=64, BK=16, 256 threads, 4x4 per thread. K total = 512 (two 256 halves).
template <bool RELU, bool TO_H>
__global__ void k_gemm(const float* __restrict__ W0, const float* __restrict__ W1,
                       const float* __restrict__ b0, const float* __restrict__ b1,
                       float* __restrict__ Cext) {
    __shared__ float As[16][65];
    __shared__ float Bs[16][64];
    float* C = TO_H ? g_h : Cext;

    int bm = blockIdx.y * 64;
    int bn = blockIdx.x * 64;
    int tid = threadIdx.x;
    int tx = tid & 15, ty = tid >> 4;

    int la_row = tid >> 2;            // 0..63
    int la_k   = (tid & 3) * 4;       // 0,4,8,12
    int lb_k   = tid >> 4;            // 0..15
    int lb_n   = (tid & 15) * 4;      // 0..60

    float acc[4][4] = {};

    for (int kt = 0; kt < 512; kt += 16) {
        const float* A = (kt < 256) ? g_aggS : g_aggU;
        const float* W = (kt < 256) ? W0 : W1;
        int kk = kt & 255;

        int arow = bm + la_row;
        float4 av = make_float4(0.f, 0.f, 0.f, 0.f);
        if (arow < NN) av = *(const float4*)(A + (size_t)arow * DD + kk + la_k);
        As[la_k + 0][la_row] = av.x;
        As[la_k + 1][la_row] = av.y;
        As[la_k + 2][la_row] = av.z;
        As[la_k + 3][la_row] = av.w;

        float4 bv = *(const float4*)(W + (size_t)(kk + lb_k) * DD + bn + lb_n);
        *(float4*)&Bs[lb_k][lb_n] = bv;
        __syncthreads();

#pragma unroll
        for (int k = 0; k < 16; k++) {
            float ra[4], rb[4];
#pragma unroll
            for (int i = 0; i < 4; i++) ra[i] = As[k][ty * 4 + i];
#pragma unroll
            for (int j = 0; j < 4; j++) rb[j] = Bs[k][tx * 4 + j];
#pragma unroll
            for (int i = 0; i < 4; i++)
#pragma unroll
                for (int j = 0; j < 4; j++) acc[i][j] += ra[i] * rb[j];
        }
        __syncthreads();
    }

#pragma unroll
    for (int i = 0; i < 4; i++) {
        int m = bm + ty * 4 + i;
        if (m >= NN) continue;
#pragma unroll
        for (int j = 0; j < 4; j++) {
            int n = bn + tx * 4 + j;
            float v = acc[i][j] + b0[n] + b1[n];
            if (RELU) v = fmaxf(v, 0.f);
            C[(size_t)m * DD + n] = v;
        }
    }
}

// ---------------- launch ----------------
extern "C" void kernel_launch(void* const* d_in, const int* in_sizes, int n_in,
                              void* d_out, int out_size) {
    const float* x    = (const float*)d_in[0];
    const int* s_src  = (const int*)d_in[1];
    const int* s_dst  = (const int*)d_in[2];
    const int* u_src  = (const int*)d_in[3];
    const int* u_dst  = (const int*)d_in[4];
    const float* W1s  = (const float*)d_in[5];
    const float* b1s  = (const float*)d_in[6];
    const float* W1u  = (const float*)d_in[7];
    const float* b1u  = (const float*)d_in[8];
    const float* W2s  = (const float*)d_in[9];
    const float* b2s  = (const float*)d_in[10];
    const float* W2u  = (const float*)d_in[11];
    const float* b2u  = (const float*)d_in[12];
    float* out = (float*)d_out;

    const int EB = (EE + 255) / 256;
    const int NB = (NN + 255) / 256;

    // build degrees + CSR (same for both layers)
    k_zero_cnt<<<(6 * NN + 255) / 256, 256>>>();
    k_hist<<<EB, 256>>>(s_src, s_dst, 0);
    k_hist<<<EB, 256>>>(u_src, u_dst, 1);
    k_scan<<<2, 1024>>>();
    k_fill<<<EB, 256>>>(s_src, s_dst, 0);
    k_fill<<<EB, 256>>>(u_src, u_dst, 1);
    k_rs<<<NB, 256>>>();

    dim3 ggrid(DD / 64, (NN + 63) / 64);

    // layer 1: agg from x, GEMM -> relu -> g_h
    k_agg<<<(NN + 3) / 4, 256>>>(x, 0, 0, 0);
    k_agg<<<(NN + 3) / 4, 256>>>(x, 1, 0, 1);
    k_gemm<true, true><<<ggrid, 256>>>(W1s, W1u, b1s, b1u, nullptr);

    // layer 2: agg from g_h, GEMM -> out
    k_agg<<<(NN + 3) / 4, 256>>>(nullptr, 0, 1, 0);
    k_agg<<<(NN + 3) / 4, 256>>>(nullptr, 1, 1, 1);
    k_gemm<false, false><<<ggrid, 256>>>(W2s, W2u, b2s, b2u, out);
}

// round 3
// speedup vs baseline: 1.5968x; 1.5968x over previous
#include <cuda_runtime.h>
#include <cuda_bf16.h>

#define NN 20000
#define DD 256
#define D4 64
#define EE 640000
#define MTILES 157   // ceil(20000/128)

// ---------------- static device scratch ----------------
__device__ int   g_cnt[6 * NN];
__device__ int   g_off[2 * (NN + 1)];
__device__ int   g_csr[2 * EE];
__device__ float g_rs[4 * NN];
__device__ __align__(16) float g_h[NN * DD];
__device__ __align__(16) __nv_bfloat16 g_Ahi[2][NN * DD];
__device__ __align__(16) __nv_bfloat16 g_Alo[2][NN * DD];
__device__ __align__(16) __nv_bfloat16 g_WThi[4][DD * DD];  // [layer*2+rel], W^T: [n][k]
__device__ __align__(16) __nv_bfloat16 g_WTlo[4][DD * DD];

static __device__ __forceinline__ unsigned sw64(unsigned o) { return o ^ ((o >> 3) & 0x30); }
static __device__ __forceinline__ unsigned short bf2u(__nv_bfloat16 h) {
    return *reinterpret_cast<unsigned short*>(&h);
}
static __device__ __forceinline__ unsigned smem_u32(const void* p) {
    unsigned a;
    asm("{ .reg .u64 t; cvta.to.shared.u64 t, %1; cvt.u32.u64 %0, t; }" : "=r"(a) : "l"(p));
    return a;
}
static __device__ __forceinline__ void ldmx4(unsigned addr, unsigned& r0, unsigned& r1,
                                             unsigned& r2, unsigned& r3) {
    asm volatile("ldmatrix.sync.aligned.m8n8.x4.shared.b16 {%0,%1,%2,%3}, [%4];"
                 : "=r"(r0), "=r"(r1), "=r"(r2), "=r"(r3) : "r"(addr));
}
static __device__ __forceinline__ void mma16816(float* c, const unsigned* a,
                                                unsigned b0, unsigned b1) {
    asm volatile(
        "mma.sync.aligned.m16n8k16.row.col.f32.bf16.bf16.f32 "
        "{%0,%1,%2,%3}, {%4,%5,%6,%7}, {%8,%9}, {%0,%1,%2,%3};"
        : "+f"(c[0]), "+f"(c[1]), "+f"(c[2]), "+f"(c[3])
        : "r"(a[0]), "r"(a[1]), "r"(a[2]), "r"(a[3]), "r"(b0), "r"(b1));
}
static __device__ __forceinline__ void sts128(unsigned a, uint4 v) {
    asm volatile("st.shared.v4.b32 [%0], {%1,%2,%3,%4};"
                 :: "r"(a), "r"(v.x), "r"(v.y), "r"(v.z), "r"(v.w) : "memory");
}

// ---------------- setup kernels ----------------
__global__ void k_zero_cnt() {
    int i = blockIdx.x * blockDim.x + threadIdx.x;
    if (i < 6 * NN) g_cnt[i] = 0;
}

__global__ void k_hist2(const int* __restrict__ s0, const int* __restrict__ d0,
                        const int* __restrict__ s1, const int* __restrict__ d1) {
    int rel = blockIdx.y;
    const int* src = rel ? s1 : s0;
    const int* dst = rel ? d1 : d0;
    int i = blockIdx.x * blockDim.x + threadIdx.x;
    if (i >= EE) return;
    atomicAdd(&g_cnt[rel * NN + src[i]], 1);
    atomicAdd(&g_cnt[2 * NN + rel * NN + dst[i]], 1);
}

// fast exclusive scan: one block of 1024 per relation, 20 elems/thread
__global__ void k_scan2() {
    int rel = blockIdx.x;
    const int* cnt = g_cnt + 2 * NN + rel * NN;
    int* off = g_off + rel * (NN + 1);
    int t = threadIdx.x, lane = t & 31, w = t >> 5;
    int base = t * 20;
    int v[20];
    int run = 0;
#pragma unroll
    for (int j = 0; j < 20; j++) {
        int i = base + j;
        int c = (i < NN) ? cnt[i] : 0;
        run += c;
        v[j] = run;
    }
    int x = run;
#pragma unroll
    for (int d = 1; d < 32; d <<= 1) {
        int y = __shfl_up_sync(0xffffffffu, x, d);
        if (lane >= d) x += y;
    }
    __shared__ int wsum[32];
    if (lane == 31) wsum[w] = x;
    __syncthreads();
    if (w == 0) {
        int s = wsum[lane];
#pragma unroll
        for (int d = 1; d < 32; d <<= 1) {
            int y = __shfl_up_sync(0xffffffffu, s, d);
            if (lane >= d) s += y;
        }
        wsum[lane] = s;
    }
    __syncthreads();
    int excl = x - run + (w > 0 ? wsum[w - 1] : 0);
#pragma unroll
    for (int j = 0; j < 20; j++) {
        int i = base + j;
        if (i < NN) off[i + 1] = excl + v[j];
    }
    if (t == 0) off[0] = 0;
}

__global__ void k_fill2(const int* __restrict__ s0, const int* __restrict__ d0,
                        const int* __restrict__ s1, const int* __restrict__ d1) {
    int rel = blockIdx.y;
    const int* src = rel ? s1 : s0;
    const int* dst = rel ? d1 : d0;
    int i = blockIdx.x * blockDim.x + threadIdx.x;
    if (i >= EE) return;
    int d = dst[i];
    int pos = atomicAdd(&g_cnt[4 * NN + rel * NN + d], 1);
    g_csr[rel * EE + g_off[rel * (NN + 1) + d] + pos] = src[i];
}

__global__ void k_rs() {
    int i = blockIdx.x * blockDim.x + threadIdx.x;
    if (i >= NN) return;
#pragma unroll
    for (int rel = 0; rel < 2; rel++) {
        float co = (float)g_cnt[rel * NN + i];
        float ci = (float)g_cnt[2 * NN + rel * NN + i];
        g_rs[rel * NN + i]          = rsqrtf(fmaxf(co, 1.0f));
        g_rs[2 * NN + rel * NN + i] = rsqrtf(fmaxf(ci, 1.0f));
    }
}

// transpose + bf16 hi/lo split of the 4 weight matrices: WT[n][k] = W[k][n]
__global__ void k_wprep(const float* __restrict__ W0, const float* __restrict__ W1,
                        const float* __restrict__ W2, const float* __restrict__ W3) {
    int m = blockIdx.y;
    const float* W = (m == 0) ? W0 : (m == 1) ? W1 : (m == 2) ? W2 : W3;
    int e = blockIdx.x * blockDim.x + threadIdx.x;
    int n = e >> 8, k = e & 255;
    float v = W[k * DD + n];
    __nv_bfloat16 hi = __float2bfloat16(v);
    float lo = v - __bfloat162float(hi);
    g_WThi[m][e] = hi;
    g_WTlo[m][e] = __float2bfloat16(lo);
}

// ---------------- aggregation (fp32 accumulate, bf16 hi/lo output) ----------------
__global__ void k_agg(const float* __restrict__ xext, int use_h) {
    int rel = blockIdx.y;
    int node = blockIdx.x * 4 + (threadIdx.x >> 6);
    int t = threadIdx.x & 63;
    if (node >= NN) return;

    const float4* x4 = (const float4*)(use_h ? (const float*)g_h : xext);
    const int* off = g_off + rel * (NN + 1);
    const int* csr = g_csr + rel * EE;
    const float* rs_out = g_rs + rel * NN;

    int beg = off[node], end = off[node + 1];
    float4 acc = make_float4(0.f, 0.f, 0.f, 0.f);
    for (int e = beg; e < end; e++) {
        int s = __ldg(&csr[e]);
        float sc = __ldg(&rs_out[s]);
        float4 v = __ldg(&x4[(size_t)s * D4 + t]);
        acc.x += v.x * sc; acc.y += v.y * sc; acc.z += v.z * sc; acc.w += v.w * sc;
    }
    float ri = g_rs[2 * NN + rel * NN + node];
    acc.x *= ri; acc.y *= ri; acc.z *= ri; acc.w *= ri;

    __nv_bfloat16 h0 = __float2bfloat16(acc.x);
    __nv_bfloat16 h1 = __float2bfloat16(acc.y);
    __nv_bfloat16 h2 = __float2bfloat16(acc.z);
    __nv_bfloat16 h3 = __float2bfloat16(acc.w);
    ushort4 hv = make_ushort4(bf2u(h0), bf2u(h1), bf2u(h2), bf2u(h3));
    ushort4 lv = make_ushort4(
        bf2u(__float2bfloat16(acc.x - __bfloat162float(h0))),
        bf2u(__float2bfloat16(acc.y - __bfloat162float(h1))),
        bf2u(__float2bfloat16(acc.z - __bfloat162float(h2))),
        bf2u(__float2bfloat16(acc.w - __bfloat162float(h3))));
    *reinterpret_cast<ushort4*>(&g_Ahi[rel][(size_t)node * DD + 4 * t]) = hv;
    *reinterpret_cast<ushort4*>(&g_Alo[rel][(size_t)node * DD + 4 * t]) = lv;
}

// ---------------- HMMA GEMM: C = aggS@W_s + aggU@W_u + b0 + b1 (+relu) -----------
// bf16x3 split -> 6 terms x K=256 = effective K 1536, K-chunks of 32 (48 chunks).
// CTA 128(M) x 128(N), 8 warps, warp tile 32x64 (2 m16 x 8 n8 mma tiles).
template <bool RELU, bool TO_H>
__global__ void __launch_bounds__(256)
k_hgemm(int layer, const float* __restrict__ b0v, const float* __restrict__ b1v,
        float* __restrict__ Cext) {
    __shared__ __align__(1024) char smA[2][8192];   // [128 m][32 k] bf16, SW64 rows
    __shared__ __align__(1024) char smB[2][8192];   // [128 n][32 k] bf16, SW64 rows

    const int tid = threadIdx.x;
    const int lane = tid & 31;
    const int wid = tid >> 5;
    const int wm = wid >> 1;           // 0..3 -> m offset wm*32
    const int wn = wid & 1;            // 0..1 -> n offset wn*64
    const int bm = blockIdx.y * 128;
    const int bn = blockIdx.x * 128;
    float* C = TO_H ? g_h : Cext;

    const __nv_bfloat16* AhiS = g_Ahi[0];
    const __nv_bfloat16* AloS = g_Alo[0];
    const __nv_bfloat16* AhiU = g_Ahi[1];
    const __nv_bfloat16* AloU = g_Alo[1];
    const __nv_bfloat16* BhiS = g_WThi[layer * 2 + 0];
    const __nv_bfloat16* BloS = g_WTlo[layer * 2 + 0];
    const __nv_bfloat16* BhiU = g_WThi[layer * 2 + 1];
    const __nv_bfloat16* BloU = g_WTlo[layer * 2 + 1];

    // ldmatrix source addresses (lane-constant, swizzled once)
    unsigned aBase = smem_u32(&smA[0][0]);
    unsigned bBase = smem_u32(&smB[0][0]);
    // A x4: mi=lane>>3: row += (mi&1)*8, chunk16 += (mi>>1)
    unsigned aoff = (unsigned)((wm * 32 + ((lane >> 3) & 1) * 8 + (lane & 7)) * 64
                               + ((lane >> 4) & 1) * 16);
    // B x4: mi: nt += (mi>>1), chunk16 += (mi&1)
    unsigned boff = (unsigned)((wn * 64 + ((lane >> 4) & 1) * 8 + (lane & 7)) * 64
                               + ((lane >> 3) & 1) * 16);
    unsigned aAdr[2][2], bAdr[2][2];   // [buf][ks]
#pragma unroll
    for (int buf = 0; buf < 2; buf++)
#pragma unroll
        for (int ks = 0; ks < 2; ks++) {
            aAdr[buf][ks] = aBase + buf * 8192 + sw64(aoff + ks * 32);
            bAdr[buf][ks] = bBase + buf * 8192 + sw64(boff + ks * 32);
        }

    // global->smem staging indices: idx = tid, tid+256 -> row=idx>>2, chunk=idx&3
    const int r0 = tid >> 2, ch = tid & 3;
    unsigned stA0 = sw64((unsigned)(r0 * 64 + ch * 16));
    unsigned stA1 = sw64((unsigned)((r0 + 64) * 64 + ch * 16));

    float acc[2][8][4];
#pragma unroll
    for (int i = 0; i < 2; i++)
#pragma unroll
        for (int j = 0; j < 8; j++)
#pragma unroll
            for (int q = 0; q < 4; q++) acc[i][j][q] = 0.f;

    uint4 sa0, sa1, sb0, sb1;
    // prologue: load chunk 0
    {
        const __nv_bfloat16* Ag = AhiS;
        const __nv_bfloat16* Bg = BhiS;
        int gr0 = bm + r0, gr1 = bm + 64 + r0;
        sa0 = (gr0 < NN) ? *(const uint4*)(Ag + (size_t)gr0 * DD + ch * 8) : make_uint4(0,0,0,0);
        sa1 = (gr1 < NN) ? *(const uint4*)(Ag + (size_t)gr1 * DD + ch * 8) : make_uint4(0,0,0,0);
        sb0 = *(const uint4*)(Bg + (size_t)(bn + r0) * DD + ch * 8);
        sb1 = *(const uint4*)(Bg + (size_t)(bn + 64 + r0) * DD + ch * 8);
        sts128(aBase + stA0, sa0);
        sts128(aBase + stA1, sa1);
        sts128(bBase + stA0, sb0);
        sts128(bBase + stA1, sb1);
    }
    __syncthreads();

    for (int c = 0; c < 48; c++) {
        int buf = c & 1;
        // issue global loads for chunk c+1
        if (c + 1 < 48) {
            int cn = c + 1;
            int term = cn >> 3;
            int kk = (cn & 7) * 32;
            const __nv_bfloat16* Ag = (term < 3) ? ((term == 1) ? AloS : AhiS)
                                                 : ((term == 4) ? AloU : AhiU);
            const __nv_bfloat16* Bg = (term < 3) ? ((term == 2) ? BloS : BhiS)
                                                 : ((term == 5) ? BloU : BhiU);
            int gr0 = bm + r0, gr1 = bm + 64 + r0;
            sa0 = (gr0 < NN) ? *(const uint4*)(Ag + (size_t)gr0 * DD + kk + ch * 8) : make_uint4(0,0,0,0);
            sa1 = (gr1 < NN) ? *(const uint4*)(Ag + (size_t)gr1 * DD + kk + ch * 8) : make_uint4(0,0,0,0);
            sb0 = *(const uint4*)(Bg + (size_t)(bn + r0) * DD + kk + ch * 8);
            sb1 = *(const uint4*)(Bg + (size_t)(bn + 64 + r0) * DD + kk + ch * 8);
        }

        // MMA on buf
#pragma unroll
        for (int ks = 0; ks < 2; ks++) {
            unsigned a[2][4];
            ldmx4(aAdr[buf][ks],        a[0][0], a[0][1], a[0][2], a[0][3]);
            ldmx4(aAdr[buf][ks] + 1024, a[1][0], a[1][1], a[1][2], a[1][3]);
#pragma unroll
            for (int p = 0; p < 4; p++) {
                unsigned bb0, bb1, bb2, bb3;
                ldmx4(bAdr[buf][ks] + p * 1024, bb0, bb1, bb2, bb3);
#pragma unroll
                for (int mt = 0; mt < 2; mt++) {
                    mma16816(acc[mt][2 * p + 0], a[mt], bb0, bb1);
                    mma16816(acc[mt][2 * p + 1], a[mt], bb2, bb3);
                }
            }
        }

        if (c + 1 < 48) {
            unsigned ab = aBase + (buf ^ 1) * 8192;
            unsigned bb = bBase + (buf ^ 1) * 8192;
            sts128(ab + stA0, sa0);
            sts128(ab + stA1, sa1);
            sts128(bb + stA0, sb0);
            sts128(bb + stA1, sb1);
        }
        __syncthreads();
    }

    // epilogue: bias + (relu) + store, fragment layout direct to global
#pragma unroll
    for (int nt = 0; nt < 8; nt++) {
        int col = bn + wn * 64 + nt * 8 + (lane & 3) * 2;
        float bs0 = b0v[col] + b1v[col];
        float bs1 = b0v[col + 1] + b1v[col + 1];
#pragma unroll
        for (int mt = 0; mt < 2; mt++) {
            int row = bm + wm * 32 + mt * 16 + (lane >> 2);
            if (row < NN) {
                float2 v;
                v.x = acc[mt][nt][0] + bs0;
                v.y = acc[mt][nt][1] + bs1;
                if (RELU) { v.x = fmaxf(v.x, 0.f); v.y = fmaxf(v.y, 0.f); }
                *(float2*)(C + (size_t)row * DD + col) = v;
            }
            int row2 = row + 8;
            if (row2 < NN) {
                float2 v;
                v.x = acc[mt][nt][2] + bs0;
                v.y = acc[mt][nt][3] + bs1;
                if (RELU) { v.x = fmaxf(v.x, 0.f); v.y = fmaxf(v.y, 0.f); }
                *(float2*)(C + (size_t)row2 * DD + col) = v;
            }
        }
    }
}

// ---------------- launch ----------------
extern "C" void kernel_launch(void* const* d_in, const int* in_sizes, int n_in,
                              void* d_out, int out_size) {
    const float* x    = (const float*)d_in[0];
    const int* s_src  = (const int*)d_in[1];
    const int* s_dst  = (const int*)d_in[2];
    const int* u_src  = (const int*)d_in[3];
    const int* u_dst  = (const int*)d_in[4];
    const float* W1s  = (const float*)d_in[5];
    const float* b1s  = (const float*)d_in[6];
    const float* W1u  = (const float*)d_in[7];
    const float* b1u  = (const float*)d_in[8];
    const float* W2s  = (const float*)d_in[9];
    const float* b2s  = (const float*)d_in[10];
    const float* W2u  = (const float*)d_in[11];
    const float* b2u  = (const float*)d_in[12];
    float* out = (float*)d_out;

    const int EB = (EE + 255) / 256;

    k_zero_cnt<<<(6 * NN + 255) / 256, 256>>>();
    k_hist2<<<dim3(EB, 2), 256>>>(s_src, s_dst, u_src, u_dst);
    k_scan2<<<2, 1024>>>();
    k_fill2<<<dim3(EB, 2), 256>>>(s_src, s_dst, u_src, u_dst);
    k_rs<<<(NN + 255) / 256, 256>>>();
    k_wprep<<<dim3(DD * DD / 256, 4), 256>>>(W1s, W1u, W2s, W2u);

    dim3 ggrid(2, MTILES);

    // layer 1
    k_agg<<<dim3((NN + 3) / 4, 2), 256>>>(x, 0);
    k_hgemm<true, true><<<ggrid, 256>>>(0, b1s, b1u, nullptr);
    // layer 2
    k_agg<<<dim3((NN + 3) / 4, 2), 256>>>(nullptr, 1);
    k_hgemm<false, false><<<ggrid, 256>>>(1, b2s, b2u, out);
}

// round 4
// speedup vs baseline: 1.8625x; 1.1664x over previous
#include <cuda_runtime.h>
#include <cuda_bf16.h>
#include <cuda_fp16.h>

#define NN 20000
#define DD 256
#define D4 64
#define EE 640000
#define MTILES 157   // ceil(20000/128)

// ---------------- static device scratch ----------------
__device__ int   g_cnt[6 * NN];
__device__ int   g_off[2 * (NN + 1)];
__device__ int   g_csr[2 * EE];
__device__ float g_rs[4 * NN];
__device__ __align__(16) __half g_xh[NN * DD];              // fp16 gather operand (x, then h)
__device__ __align__(16) __nv_bfloat16 g_Ahi[2][NN * DD];
__device__ __align__(16) __nv_bfloat16 g_Alo[2][NN * DD];
__device__ __align__(16) __nv_bfloat16 g_WThi[4][DD * DD];  // [layer*2+rel], W^T: [n][k]
__device__ __align__(16) __nv_bfloat16 g_WTlo[4][DD * DD];

static __device__ __forceinline__ unsigned sw64(unsigned o) { return o ^ ((o >> 3) & 0x30); }
static __device__ __forceinline__ unsigned short bf2u(__nv_bfloat16 h) {
    return *reinterpret_cast<unsigned short*>(&h);
}
static __device__ __forceinline__ unsigned smem_u32(const void* p) {
    unsigned a;
    asm("{ .reg .u64 t; cvta.to.shared.u64 t, %1; cvt.u32.u64 %0, t; }" : "=r"(a) : "l"(p));
    return a;
}
static __device__ __forceinline__ void ldmx4(unsigned addr, unsigned& r0, unsigned& r1,
                                             unsigned& r2, unsigned& r3) {
    asm volatile("ldmatrix.sync.aligned.m8n8.x4.shared.b16 {%0,%1,%2,%3}, [%4];"
                 : "=r"(r0), "=r"(r1), "=r"(r2), "=r"(r3) : "r"(addr));
}
static __device__ __forceinline__ void mma16816(float* c, const unsigned* a,
                                                unsigned b0, unsigned b1) {
    asm volatile(
        "mma.sync.aligned.m16n8k16.row.col.f32.bf16.bf16.f32 "
        "{%0,%1,%2,%3}, {%4,%5,%6,%7}, {%8,%9}, {%0,%1,%2,%3};"
        : "+f"(c[0]), "+f"(c[1]), "+f"(c[2]), "+f"(c[3])
        : "r"(a[0]), "r"(a[1]), "r"(a[2]), "r"(a[3]), "r"(b0), "r"(b1));
}
static __device__ __forceinline__ void sts128(unsigned a, uint4 v) {
    asm volatile("st.shared.v4.b32 [%0], {%1,%2,%3,%4};"
                 :: "r"(a), "r"(v.x), "r"(v.y), "r"(v.z), "r"(v.w) : "memory");
}

// ---------------- setup kernels ----------------
__global__ void k_zero_cnt() {
    int i = blockIdx.x * blockDim.x + threadIdx.x;
    if (i < 6 * NN) g_cnt[i] = 0;
}

__global__ void k_hist2(const int* __restrict__ s0, const int* __restrict__ d0,
                        const int* __restrict__ s1, const int* __restrict__ d1) {
    int rel = blockIdx.y;
    const int* src = rel ? s1 : s0;
    const int* dst = rel ? d1 : d0;
    int i = blockIdx.x * blockDim.x + threadIdx.x;
    if (i >= EE) return;
    atomicAdd(&g_cnt[rel * NN + src[i]], 1);
    atomicAdd(&g_cnt[2 * NN + rel * NN + dst[i]], 1);
}

// fast exclusive scan: one block of 1024 per relation, 20 elems/thread
__global__ void k_scan2() {
    int rel = blockIdx.x;
    const int* cnt = g_cnt + 2 * NN + rel * NN;
    int* off = g_off + rel * (NN + 1);
    int t = threadIdx.x, lane = t & 31, w = t >> 5;
    int base = t * 20;
    int v[20];
    int run = 0;
#pragma unroll
    for (int j = 0; j < 20; j++) {
        int i = base + j;
        int c = (i < NN) ? cnt[i] : 0;
        run += c;
        v[j] = run;
    }
    int x = run;
#pragma unroll
    for (int d = 1; d < 32; d <<= 1) {
        int y = __shfl_up_sync(0xffffffffu, x, d);
        if (lane >= d) x += y;
    }
    __shared__ int wsum[32];
    if (lane == 31) wsum[w] = x;
    __syncthreads();
    if (w == 0) {
        int s = wsum[lane];
#pragma unroll
        for (int d = 1; d < 32; d <<= 1) {
            int y = __shfl_up_sync(0xffffffffu, s, d);
            if (lane >= d) s += y;
        }
        wsum[lane] = s;
    }
    __syncthreads();
    int excl = x - run + (w > 0 ? wsum[w - 1] : 0);
#pragma unroll
    for (int j = 0; j < 20; j++) {
        int i = base + j;
        if (i < NN) off[i + 1] = excl + v[j];
    }
    if (t == 0) off[0] = 0;
}

__global__ void k_fill2(const int* __restrict__ s0, const int* __restrict__ d0,
                        const int* __restrict__ s1, const int* __restrict__ d1) {
    int rel = blockIdx.y;
    const int* src = rel ? s1 : s0;
    const int* dst = rel ? d1 : d0;
    int i = blockIdx.x * blockDim.x + threadIdx.x;
    if (i >= EE) return;
    int d = dst[i];
    int pos = atomicAdd(&g_cnt[4 * NN + rel * NN + d], 1);
    g_csr[rel * EE + g_off[rel * (NN + 1) + d] + pos] = src[i];
}

__global__ void k_rs() {
    int i = blockIdx.x * blockDim.x + threadIdx.x;
    if (i >= NN) return;
#pragma unroll
    for (int rel = 0; rel < 2; rel++) {
        float co = (float)g_cnt[rel * NN + i];
        float ci = (float)g_cnt[2 * NN + rel * NN + i];
        g_rs[rel * NN + i]          = rsqrtf(fmaxf(co, 1.0f));
        g_rs[2 * NN + rel * NN + i] = rsqrtf(fmaxf(ci, 1.0f));
    }
}

// transpose + bf16 hi/lo split of the 4 weight matrices: WT[n][k] = W[k][n]
__global__ void k_wprep(const float* __restrict__ W0, const float* __restrict__ W1,
                        const float* __restrict__ W2, const float* __restrict__ W3) {
    int m = blockIdx.y;
    const float* W = (m == 0) ? W0 : (m == 1) ? W1 : (m == 2) ? W2 : W3;
    int e = blockIdx.x * blockDim.x + threadIdx.x;
    int n = e >> 8, k = e & 255;
    float v = W[k * DD + n];
    __nv_bfloat16 hi = __float2bfloat16(v);
    float lo = v - __bfloat162float(hi);
    g_WThi[m][e] = hi;
    g_WTlo[m][e] = __float2bfloat16(lo);
}

// x (fp32) -> g_xh (fp16)
__global__ void k_xcvt(const float* __restrict__ x) {
    int i = blockIdx.x * blockDim.x + threadIdx.x;   // one float4 each
    if (i >= NN * D4) return;
    float4 v = ((const float4*)x)[i];
    uint2 o;
    *(half2*)&o.x = __floats2half2_rn(v.x, v.y);
    *(half2*)&o.y = __floats2half2_rn(v.z, v.w);
    ((uint2*)g_xh)[i] = o;
}

// ---------------- aggregation: fp16 gather rows, fp32 accumulate, bf16 hi/lo out --
// 32 threads per node (one uint4 = 8 halves per thread), 8 nodes per 256-block.
__global__ void k_agg() {
    int rel = blockIdx.y;
    int node = blockIdx.x * 8 + (threadIdx.x >> 5);
    int t = threadIdx.x & 31;
    if (node >= NN) return;

    const uint4* x4 = (const uint4*)g_xh;   // 32 uint4 per 512B row
    const int* off = g_off + rel * (NN + 1);
    const int* csr = g_csr + rel * EE;
    const float* rs_out = g_rs + rel * NN;

    int beg = off[node], end = off[node + 1];
    float acc[8] = {0.f, 0.f, 0.f, 0.f, 0.f, 0.f, 0.f, 0.f};
#pragma unroll 2
    for (int e = beg; e < end; e++) {
        int s = __ldg(&csr[e]);
        float sc = __ldg(&rs_out[s]);
        uint4 v = __ldg(&x4[s * 32 + t]);
        float2 f0 = __half22float2(*(half2*)&v.x);
        float2 f1 = __half22float2(*(half2*)&v.y);
        float2 f2 = __half22float2(*(half2*)&v.z);
        float2 f3 = __half22float2(*(half2*)&v.w);
        acc[0] += f0.x * sc; acc[1] += f0.y * sc;
        acc[2] += f1.x * sc; acc[3] += f1.y * sc;
        acc[4] += f2.x * sc; acc[5] += f2.y * sc;
        acc[6] += f3.x * sc; acc[7] += f3.y * sc;
    }
    float ri = g_rs[2 * NN + rel * NN + node];

    unsigned short hi[8], lo[8];
#pragma unroll
    for (int j = 0; j < 8; j++) {
        float val = acc[j] * ri;
        __nv_bfloat16 h = __float2bfloat16(val);
        hi[j] = bf2u(h);
        lo[j] = bf2u(__float2bfloat16(val - __bfloat162float(h)));
    }
    *(uint4*)&g_Ahi[rel][(size_t)node * DD + t * 8] = *(uint4*)hi;
    *(uint4*)&g_Alo[rel][(size_t)node * DD + t * 8] = *(uint4*)lo;
}

// ---------------- HMMA GEMM: C = aggS@W_s + aggU@W_u + b0 + b1 (+relu) -----------
// bf16x3 split -> 6 terms x K=256 = effective K 1536, K-chunks of 32 (48 chunks).
// CTA 128(M) x 128(N), 8 warps, warp tile 32x64 (2 m16 x 8 n8 mma tiles).
// TO_H: write h as fp16 into g_xh; else write fp32 to Cext.
template <bool RELU, bool TO_H>
__global__ void __launch_bounds__(256)
k_hgemm(int layer, const float* __restrict__ b0v, const float* __restrict__ b1v,
        float* __restrict__ Cext) {
    __shared__ __align__(1024) char smA[2][8192];   // [128 m][32 k] bf16, SW64 rows
    __shared__ __align__(1024) char smB[2][8192];   // [128 n][32 k] bf16, SW64 rows

    const int tid = threadIdx.x;
    const int lane = tid & 31;
    const int wid = tid >> 5;
    const int wm = wid >> 1;           // 0..3 -> m offset wm*32
    const int wn = wid & 1;            // 0..1 -> n offset wn*64
    const int bm = blockIdx.y * 128;
    const int bn = blockIdx.x * 128;

    const __nv_bfloat16* AhiS = g_Ahi[0];
    const __nv_bfloat16* AloS = g_Alo[0];
    const __nv_bfloat16* AhiU = g_Ahi[1];
    const __nv_bfloat16* AloU = g_Alo[1];
    const __nv_bfloat16* BhiS = g_WThi[layer * 2 + 0];
    const __nv_bfloat16* BloS = g_WTlo[layer * 2 + 0];
    const __nv_bfloat16* BhiU = g_WThi[layer * 2 + 1];
    const __nv_bfloat16* BloU = g_WTlo[layer * 2 + 1];

    unsigned aBase = smem_u32(&smA[0][0]);
    unsigned bBase = smem_u32(&smB[0][0]);
    unsigned aoff = (unsigned)((wm * 32 + ((lane >> 3) & 1) * 8 + (lane & 7)) * 64
                               + ((lane >> 4) & 1) * 16);
    unsigned boff = (unsigned)((wn * 64 + ((lane >> 4) & 1) * 8 + (lane & 7)) * 64
                               + ((lane >> 3) & 1) * 16);
    unsigned aAdr[2][2], bAdr[2][2];   // [buf][ks]
#pragma unroll
    for (int buf = 0; buf < 2; buf++)
#pragma unroll
        for (int ks = 0; ks < 2; ks++) {
            aAdr[buf][ks] = aBase + buf * 8192 + sw64(aoff + ks * 32);
            bAdr[buf][ks] = bBase + buf * 8192 + sw64(boff + ks * 32);
        }

    const int r0 = tid >> 2, ch = tid & 3;
    unsigned stA0 = sw64((unsigned)(r0 * 64 + ch * 16));
    unsigned stA1 = sw64((unsigned)((r0 + 64) * 64 + ch * 16));

    float acc[2][8][4];
#pragma unroll
    for (int i = 0; i < 2; i++)
#pragma unroll
        for (int j = 0; j < 8; j++)
#pragma unroll
            for (int q = 0; q < 4; q++) acc[i][j][q] = 0.f;

    uint4 sa0, sa1, sb0, sb1;
    {
        const __nv_bfloat16* Ag = AhiS;
        const __nv_bfloat16* Bg = BhiS;
        int gr0 = bm + r0, gr1 = bm + 64 + r0;
        sa0 = (gr0 < NN) ? *(const uint4*)(Ag + (size_t)gr0 * DD + ch * 8) : make_uint4(0,0,0,0);
        sa1 = (gr1 < NN) ? *(const uint4*)(Ag + (size_t)gr1 * DD + ch * 8) : make_uint4(0,0,0,0);
        sb0 = *(const uint4*)(Bg + (size_t)(bn + r0) * DD + ch * 8);
        sb1 = *(const uint4*)(Bg + (size_t)(bn + 64 + r0) * DD + ch * 8);
        sts128(aBase + stA0, sa0);
        sts128(aBase + stA1, sa1);
        sts128(bBase + stA0, sb0);
        sts128(bBase + stA1, sb1);
    }
    __syncthreads();

    for (int c = 0; c < 48; c++) {
        int buf = c & 1;
        if (c + 1 < 48) {
            int cn = c + 1;
            int term = cn >> 3;
            int kk = (cn & 7) * 32;
            const __nv_bfloat16* Ag = (term < 3) ? ((term == 1) ? AloS : AhiS)
                                                 : ((term == 4) ? AloU : AhiU);
            const __nv_bfloat16* Bg = (term < 3) ? ((term == 2) ? BloS : BhiS)
                                                 : ((term == 5) ? BloU : BhiU);
            int gr0 = bm + r0, gr1 = bm + 64 + r0;
            sa0 = (gr0 < NN) ? *(const uint4*)(Ag + (size_t)gr0 * DD + kk + ch * 8) : make_uint4(0,0,0,0);
            sa1 = (gr1 < NN) ? *(const uint4*)(Ag + (size_t)gr1 * DD + kk + ch * 8) : make_uint4(0,0,0,0);
            sb0 = *(const uint4*)(Bg + (size_t)(bn + r0) * DD + kk + ch * 8);
            sb1 = *(const uint4*)(Bg + (size_t)(bn + 64 + r0) * DD + kk + ch * 8);
        }

#pragma unroll
        for (int ks = 0; ks < 2; ks++) {
            unsigned a[2][4];
            ldmx4(aAdr[buf][ks],        a[0][0], a[0][1], a[0][2], a[0][3]);
            ldmx4(aAdr[buf][ks] + 1024, a[1][0], a[1][1], a[1][2], a[1][3]);
#pragma unroll
            for (int p = 0; p < 4; p++) {
                unsigned bb0, bb1, bb2, bb3;
                ldmx4(bAdr[buf][ks] + p * 1024, bb0, bb1, bb2, bb3);
#pragma unroll
                for (int mt = 0; mt < 2; mt++) {
                    mma16816(acc[mt][2 * p + 0], a[mt], bb0, bb1);
                    mma16816(acc[mt][2 * p + 1], a[mt], bb2, bb3);
                }
            }
        }

        if (c + 1 < 48) {
            unsigned ab = aBase + (buf ^ 1) * 8192;
            unsigned bb = bBase + (buf ^ 1) * 8192;
            sts128(ab + stA0, sa0);
            sts128(ab + stA1, sa1);
            sts128(bb + stA0, sb0);
            sts128(bb + stA1, sb1);
        }
        __syncthreads();
    }

    // epilogue: bias + (relu) + store
#pragma unroll
    for (int nt = 0; nt < 8; nt++) {
        int col = bn + wn * 64 + nt * 8 + (lane & 3) * 2;
        float bs0 = b0v[col] + b1v[col];
        float bs1 = b0v[col + 1] + b1v[col + 1];
#pragma unroll
        for (int mt = 0; mt < 2; mt++) {
            int row = bm + wm * 32 + mt * 16 + (lane >> 2);
#pragma unroll
            for (int half_sel = 0; half_sel < 2; half_sel++) {
                int r = row + half_sel * 8;
                if (r < NN) {
                    float vx = acc[mt][nt][2 * half_sel + 0] + bs0;
                    float vy = acc[mt][nt][2 * half_sel + 1] + bs1;
                    if (RELU) { vx = fmaxf(vx, 0.f); vy = fmaxf(vy, 0.f); }
                    if (TO_H) {
                        *(half2*)(g_xh + (size_t)r * DD + col) = __floats2half2_rn(vx, vy);
                    } else {
                        float2 v2 = make_float2(vx, vy);
                        *(float2*)(Cext + (size_t)r * DD + col) = v2;
                    }
                }
            }
        }
    }
}

// ---------------- launch ----------------
extern "C" void kernel_launch(void* const* d_in, const int* in_sizes, int n_in,
                              void* d_out, int out_size) {
    const float* x    = (const float*)d_in[0];
    const int* s_src  = (const int*)d_in[1];
    const int* s_dst  = (const int*)d_in[2];
    const int* u_src  = (const int*)d_in[3];
    const int* u_dst  = (const int*)d_in[4];
    const float* W1s  = (const float*)d_in[5];
    const float* b1s  = (const float*)d_in[6];
    const float* W1u  = (const float*)d_in[7];
    const float* b1u  = (const float*)d_in[8];
    const float* W2s  = (const float*)d_in[9];
    const float* b2s  = (const float*)d_in[10];
    const float* W2u  = (const float*)d_in[11];
    const float* b2u  = (const float*)d_in[12];
    float* out = (float*)d_out;

    const int EB = (EE + 255) / 256;

    k_zero_cnt<<<(6 * NN + 255) / 256, 256>>>();
    k_hist2<<<dim3(EB, 2), 256>>>(s_src, s_dst, u_src, u_dst);
    k_scan2<<<2, 1024>>>();
    k_fill2<<<dim3(EB, 2), 256>>>(s_src, s_dst, u_src, u_dst);
    k_rs<<<(NN + 255) / 256, 256>>>();
    k_wprep<<<dim3(DD * DD / 256, 4), 256>>>(W1s, W1u, W2s, W2u);
    k_xcvt<<<(NN * D4 + 255) / 256, 256>>>(x);

    dim3 ggrid(2, MTILES);

    // layer 1: agg from g_xh(=x), GEMM -> relu -> g_xh(=h, fp16)
    k_agg<<<dim3((NN + 7) / 8, 2), 256>>>();
    k_hgemm<true, true><<<ggrid, 256>>>(0, b1s, b1u, nullptr);
    // layer 2: agg from g_xh(=h), GEMM -> out
    k_agg<<<dim3((NN + 7) / 8, 2), 256>>>();
    k_hgemm<false, false><<<ggrid, 256>>>(1, b2s, b2u, out);
}

// round 5
// speedup vs baseline: 2.6696x; 1.4333x over previous
#include <cuda_runtime.h>
#include <cuda_bf16.h>
#include <cuda_fp16.h>

#define NN 20000
#define DD 256
#define D4 64
#define EE 640000
#define MTILES 157   // ceil(20000/128)

// ---------------- static device scratch ----------------
__device__ int   g_cnt[6 * NN];
__device__ int   g_off[2 * (NN + 1)];
__device__ int   g_csr[2 * EE];
__device__ float g_rs[4 * NN];
__device__ __align__(16) __half g_xh[NN * DD];        // fp16 gather operand (x, then h)
__device__ __align__(16) __half g_A[2][NN * DD];      // fp16 agg outputs per relation
__device__ __align__(16) __half g_WT[4][DD * DD];     // [layer*2+rel], W^T: [n][k], fp16

static __device__ __forceinline__ unsigned sw64(unsigned o) { return o ^ ((o >> 3) & 0x30); }
static __device__ __forceinline__ unsigned smem_u32(const void* p) {
    unsigned a;
    asm("{ .reg .u64 t; cvta.to.shared.u64 t, %1; cvt.u32.u64 %0, t; }" : "=r"(a) : "l"(p));
    return a;
}
static __device__ __forceinline__ void ldmx4(unsigned addr, unsigned& r0, unsigned& r1,
                                             unsigned& r2, unsigned& r3) {
    asm volatile("ldmatrix.sync.aligned.m8n8.x4.shared.b16 {%0,%1,%2,%3}, [%4];"
                 : "=r"(r0), "=r"(r1), "=r"(r2), "=r"(r3) : "r"(addr));
}
static __device__ __forceinline__ void mma16816(float* c, const unsigned* a,
                                                unsigned b0, unsigned b1) {
    asm volatile(
        "mma.sync.aligned.m16n8k16.row.col.f32.f16.f16.f32 "
        "{%0,%1,%2,%3}, {%4,%5,%6,%7}, {%8,%9}, {%0,%1,%2,%3};"
        : "+f"(c[0]), "+f"(c[1]), "+f"(c[2]), "+f"(c[3])
        : "r"(a[0]), "r"(a[1]), "r"(a[2]), "r"(a[3]), "r"(b0), "r"(b1));
}
static __device__ __forceinline__ void sts128(unsigned a, uint4 v) {
    asm volatile("st.shared.v4.b32 [%0], {%1,%2,%3,%4};"
                 :: "r"(a), "r"(v.x), "r"(v.y), "r"(v.z), "r"(v.w) : "memory");
}

// ---------------- setup kernels ----------------
__global__ void k_zero_cnt() {
    int i = blockIdx.x * blockDim.x + threadIdx.x;
    if (i < 6 * NN) g_cnt[i] = 0;
}

__global__ void k_hist2(const int* __restrict__ s0, const int* __restrict__ d0,
                        const int* __restrict__ s1, const int* __restrict__ d1) {
    int rel = blockIdx.y;
    const int* src = rel ? s1 : s0;
    const int* dst = rel ? d1 : d0;
    int i = blockIdx.x * blockDim.x + threadIdx.x;
    if (i >= EE) return;
    atomicAdd(&g_cnt[rel * NN + src[i]], 1);
    atomicAdd(&g_cnt[2 * NN + rel * NN + dst[i]], 1);
}

// fast exclusive scan: one block of 1024 per relation, 20 elems/thread
__global__ void k_scan2() {
    int rel = blockIdx.x;
    const int* cnt = g_cnt + 2 * NN + rel * NN;
    int* off = g_off + rel * (NN + 1);
    int t = threadIdx.x, lane = t & 31, w = t >> 5;
    int base = t * 20;
    int v[20];
    int run = 0;
#pragma unroll
    for (int j = 0; j < 20; j++) {
        int i = base + j;
        int c = (i < NN) ? cnt[i] : 0;
        run += c;
        v[j] = run;
    }
    int x = run;
#pragma unroll
    for (int d = 1; d < 32; d <<= 1) {
        int y = __shfl_up_sync(0xffffffffu, x, d);
        if (lane >= d) x += y;
    }
    __shared__ int wsum[32];
    if (lane == 31) wsum[w] = x;
    __syncthreads();
    if (w == 0) {
        int s = wsum[lane];
#pragma unroll
        for (int d = 1; d < 32; d <<= 1) {
            int y = __shfl_up_sync(0xffffffffu, s, d);
            if (lane >= d) s += y;
        }
        wsum[lane] = s;
    }
    __syncthreads();
    int excl = x - run + (w > 0 ? wsum[w - 1] : 0);
#pragma unroll
    for (int j = 0; j < 20; j++) {
        int i = base + j;
        if (i < NN) off[i + 1] = excl + v[j];
    }
    if (t == 0) off[0] = 0;
}

__global__ void k_fill2(const int* __restrict__ s0, const int* __restrict__ d0,
                        const int* __restrict__ s1, const int* __restrict__ d1) {
    int rel = blockIdx.y;
    const int* src = rel ? s1 : s0;
    const int* dst = rel ? d1 : d0;
    int i = blockIdx.x * blockDim.x + threadIdx.x;
    if (i >= EE) return;
    int d = dst[i];
    int pos = atomicAdd(&g_cnt[4 * NN + rel * NN + d], 1);
    g_csr[rel * EE + g_off[rel * (NN + 1) + d] + pos] = src[i];
}

__global__ void k_rs() {
    int i = blockIdx.x * blockDim.x + threadIdx.x;
    if (i >= NN) return;
#pragma unroll
    for (int rel = 0; rel < 2; rel++) {
        float co = (float)g_cnt[rel * NN + i];
        float ci = (float)g_cnt[2 * NN + rel * NN + i];
        g_rs[rel * NN + i]          = rsqrtf(fmaxf(co, 1.0f));
        g_rs[2 * NN + rel * NN + i] = rsqrtf(fmaxf(ci, 1.0f));
    }
}

// transpose + fp16 convert of the 4 weight matrices: WT[n][k] = W[k][n]
__global__ void k_wprep(const float* __restrict__ W0, const float* __restrict__ W1,
                        const float* __restrict__ W2, const float* __restrict__ W3) {
    int m = blockIdx.y;
    const float* W = (m == 0) ? W0 : (m == 1) ? W1 : (m == 2) ? W2 : W3;
    int e = blockIdx.x * blockDim.x + threadIdx.x;
    int n = e >> 8, k = e & 255;
    g_WT[m][e] = __float2half_rn(W[k * DD + n]);
}

// x (fp32) -> g_xh (fp16)
__global__ void k_xcvt(const float* __restrict__ x) {
    int i = blockIdx.x * blockDim.x + threadIdx.x;   // one float4 each
    if (i >= NN * D4) return;
    float4 v = ((const float4*)x)[i];
    uint2 o;
    *(half2*)&o.x = __floats2half2_rn(v.x, v.y);
    *(half2*)&o.y = __floats2half2_rn(v.z, v.w);
    ((uint2*)g_xh)[i] = o;
}

// ---------------- aggregation: fp16 gather rows, fp32 accumulate, fp16 out -------
// 32 threads per node (one uint4 = 8 halves per thread), 8 nodes per 256-block.
__global__ void k_agg() {
    int rel = blockIdx.y;
    int node = blockIdx.x * 8 + (threadIdx.x >> 5);
    int t = threadIdx.x & 31;
    if (node >= NN) return;

    const uint4* x4 = (const uint4*)g_xh;   // 32 uint4 per 512B row
    const int* off = g_off + rel * (NN + 1);
    const int* csr = g_csr + rel * EE;
    const float* rs_out = g_rs + rel * NN;

    int beg = off[node], end = off[node + 1];
    float acc[8] = {0.f, 0.f, 0.f, 0.f, 0.f, 0.f, 0.f, 0.f};
#pragma unroll 4
    for (int e = beg; e < end; e++) {
        int s = __ldg(&csr[e]);
        float sc = __ldg(&rs_out[s]);
        uint4 v = __ldg(&x4[s * 32 + t]);
        float2 f0 = __half22float2(*(half2*)&v.x);
        float2 f1 = __half22float2(*(half2*)&v.y);
        float2 f2 = __half22float2(*(half2*)&v.z);
        float2 f3 = __half22float2(*(half2*)&v.w);
        acc[0] += f0.x * sc; acc[1] += f0.y * sc;
        acc[2] += f1.x * sc; acc[3] += f1.y * sc;
        acc[4] += f2.x * sc; acc[5] += f2.y * sc;
        acc[6] += f3.x * sc; acc[7] += f3.y * sc;
    }
    float ri = g_rs[2 * NN + rel * NN + node];

    uint4 o;
    half2* oh = (half2*)&o;
#pragma unroll
    for (int j = 0; j < 4; j++)
        oh[j] = __floats2half2_rn(acc[2 * j] * ri, acc[2 * j + 1] * ri);
    *(uint4*)&g_A[rel][(size_t)node * DD + t * 8] = o;
}

// ---------------- HMMA GEMM: C = aggS@W_s + aggU@W_u + b0 + b1 (+relu) -----------
// fp16 operands, fp32 accum. 2 terms x K=256 = effective K 512, chunks of 32 (16).
// CTA 128(M) x 128(N), 8 warps, warp tile 32x64 (2 m16 x 8 n8 mma tiles).
// TO_H: write h as fp16 into g_xh; else write fp32 to Cext.
template <bool RELU, bool TO_H>
__global__ void __launch_bounds__(256)
k_hgemm(int layer, const float* __restrict__ b0v, const float* __restrict__ b1v,
        float* __restrict__ Cext) {
    __shared__ __align__(1024) char smA[2][8192];   // [128 m][32 k] f16, SW64 rows
    __shared__ __align__(1024) char smB[2][8192];   // [128 n][32 k] f16, SW64 rows

    const int tid = threadIdx.x;
    const int lane = tid & 31;
    const int wid = tid >> 5;
    const int wm = wid >> 1;           // 0..3 -> m offset wm*32
    const int wn = wid & 1;            // 0..1 -> n offset wn*64
    const int bm = blockIdx.y * 128;
    const int bn = blockIdx.x * 128;

    const __half* AS = g_A[0];
    const __half* AU = g_A[1];
    const __half* BS = g_WT[layer * 2 + 0];
    const __half* BU = g_WT[layer * 2 + 1];

    unsigned aBase = smem_u32(&smA[0][0]);
    unsigned bBase = smem_u32(&smB[0][0]);
    unsigned aoff = (unsigned)((wm * 32 + ((lane >> 3) & 1) * 8 + (lane & 7)) * 64
                               + ((lane >> 4) & 1) * 16);
    unsigned boff = (unsigned)((wn * 64 + ((lane >> 4) & 1) * 8 + (lane & 7)) * 64
                               + ((lane >> 3) & 1) * 16);
    unsigned aAdr[2][2], bAdr[2][2];   // [buf][ks]
#pragma unroll
    for (int buf = 0; buf < 2; buf++)
#pragma unroll
        for (int ks = 0; ks < 2; ks++) {
            aAdr[buf][ks] = aBase + buf * 8192 + sw64(aoff + ks * 32);
            bAdr[buf][ks] = bBase + buf * 8192 + sw64(boff + ks * 32);
        }

    const int r0 = tid >> 2, ch = tid & 3;
    unsigned stA0 = sw64((unsigned)(r0 * 64 + ch * 16));
    unsigned stA1 = sw64((unsigned)((r0 + 64) * 64 + ch * 16));

    float acc[2][8][4];
#pragma unroll
    for (int i = 0; i < 2; i++)
#pragma unroll
        for (int j = 0; j < 8; j++)
#pragma unroll
            for (int q = 0; q < 4; q++) acc[i][j][q] = 0.f;

    uint4 sa0, sa1, sb0, sb1;
    {
        int gr0 = bm + r0, gr1 = bm + 64 + r0;
        sa0 = (gr0 < NN) ? *(const uint4*)(AS + (size_t)gr0 * DD + ch * 8) : make_uint4(0,0,0,0);
        sa1 = (gr1 < NN) ? *(const uint4*)(AS + (size_t)gr1 * DD + ch * 8) : make_uint4(0,0,0,0);
        sb0 = *(const uint4*)(BS + (size_t)(bn + r0) * DD + ch * 8);
        sb1 = *(const uint4*)(BS + (size_t)(bn + 64 + r0) * DD + ch * 8);
        sts128(aBase + stA0, sa0);
        sts128(aBase + stA1, sa1);
        sts128(bBase + stA0, sb0);
        sts128(bBase + stA1, sb1);
    }
    __syncthreads();

    for (int c = 0; c < 16; c++) {
        int buf = c & 1;
        if (c + 1 < 16) {
            int cn = c + 1;
            int term = cn >> 3;
            int kk = (cn & 7) * 32;
            const __half* Ag = term ? AU : AS;
            const __half* Bg = term ? BU : BS;
            int gr0 = bm + r0, gr1 = bm + 64 + r0;
            sa0 = (gr0 < NN) ? *(const uint4*)(Ag + (size_t)gr0 * DD + kk + ch * 8) : make_uint4(0,0,0,0);
            sa1 = (gr1 < NN) ? *(const uint4*)(Ag + (size_t)gr1 * DD + kk + ch * 8) : make_uint4(0,0,0,0);
            sb0 = *(const uint4*)(Bg + (size_t)(bn + r0) * DD + kk + ch * 8);
            sb1 = *(const uint4*)(Bg + (size_t)(bn + 64 + r0) * DD + kk + ch * 8);
        }

#pragma unroll
        for (int ks = 0; ks < 2; ks++) {
            unsigned a[2][4];
            ldmx4(aAdr[buf][ks],        a[0][0], a[0][1], a[0][2], a[0][3]);
            ldmx4(aAdr[buf][ks] + 1024, a[1][0], a[1][1], a[1][2], a[1][3]);
#pragma unroll
            for (int p = 0; p < 4; p++) {
                unsigned bb0, bb1, bb2, bb3;
                ldmx4(bAdr[buf][ks] + p * 1024, bb0, bb1, bb2, bb3);
#pragma unroll
                for (int mt = 0; mt < 2; mt++) {
                    mma16816(acc[mt][2 * p + 0], a[mt], bb0, bb1);
                    mma16816(acc[mt][2 * p + 1], a[mt], bb2, bb3);
                }
            }
        }

        if (c + 1 < 16) {
            unsigned ab = aBase + (buf ^ 1) * 8192;
            unsigned bb = bBase + (buf ^ 1) * 8192;
            sts128(ab + stA0, sa0);
            sts128(ab + stA1, sa1);
            sts128(bb + stA0, sb0);
            sts128(bb + stA1, sb1);
        }
        __syncthreads();
    }

    // epilogue: bias + (relu) + store
#pragma unroll
    for (int nt = 0; nt < 8; nt++) {
        int col = bn + wn * 64 + nt * 8 + (lane & 3) * 2;
        float bs0 = b0v[col] + b1v[col];
        float bs1 = b0v[col + 1] + b1v[col + 1];
#pragma unroll
        for (int mt = 0; mt < 2; mt++) {
            int row = bm + wm * 32 + mt * 16 + (lane >> 2);
#pragma unroll
            for (int half_sel = 0; half_sel < 2; half_sel++) {
                int r = row + half_sel * 8;
                if (r < NN) {
                    float vx = acc[mt][nt][2 * half_sel + 0] + bs0;
                    float vy = acc[mt][nt][2 * half_sel + 1] + bs1;
                    if (RELU) { vx = fmaxf(vx, 0.f); vy = fmaxf(vy, 0.f); }
                    if (TO_H) {
                        *(half2*)(g_xh + (size_t)r * DD + col) = __floats2half2_rn(vx, vy);
                    } else {
                        float2 v2 = make_float2(vx, vy);
                        *(float2*)(Cext + (size_t)r * DD + col) = v2;
                    }
                }
            }
        }
    }
}

// ---------------- launch ----------------
extern "C" void kernel_launch(void* const* d_in, const int* in_sizes, int n_in,
                              void* d_out, int out_size) {
    const float* x    = (const float*)d_in[0];
    const int* s_src  = (const int*)d_in[1];
    const int* s_dst  = (const int*)d_in[2];
    const int* u_src  = (const int*)d_in[3];
    const int* u_dst  = (const int*)d_in[4];
    const float* W1s  = (const float*)d_in[5];
    const float* b1s  = (const float*)d_in[6];
    const float* W1u  = (const float*)d_in[7];
    const float* b1u  = (const float*)d_in[8];
    const float* W2s  = (const float*)d_in[9];
    const float* b2s  = (const float*)d_in[10];
    const float* W2u  = (const float*)d_in[11];
    const float* b2u  = (const float*)d_in[12];
    float* out = (float*)d_out;

    const int EB = (EE + 255) / 256;

    k_zero_cnt<<<(6 * NN + 255) / 256, 256>>>();
    k_hist2<<<dim3(EB, 2), 256>>>(s_src, s_dst, u_src, u_dst);
    k_scan2<<<2, 1024>>>();
    k_fill2<<<dim3(EB, 2), 256>>>(s_src, s_dst, u_src, u_dst);
    k_rs<<<(NN + 255) / 256, 256>>>();
    k_wprep<<<dim3(DD * DD / 256, 4), 256>>>(W1s, W1u, W2s, W2u);
    k_xcvt<<<(NN * D4 + 255) / 256, 256>>>(x);

    dim3 ggrid(2, MTILES);

    // layer 1: agg from g_xh(=x), GEMM -> relu -> g_xh(=h, fp16)
    k_agg<<<dim3((NN + 7) / 8, 2), 256>>>();
    k_hgemm<true, true><<<ggrid, 256>>>(0, b1s, b1u, nullptr);
    // layer 2: agg from g_xh(=h), GEMM -> out
    k_agg<<<dim3((NN + 7) / 8, 2), 256>>>();
    k_hgemm<false, false><<<ggrid, 256>>>(1, b2s, b2u, out);
}